// round 17
// baseline (speedup 1.0000x reference)
#include <cuda_runtime.h>
#include <cuda_fp16.h>
#include <math.h>
#include <stdint.h>

#define BATCH 64
#define SENC  64
#define TDEC  31
#define EMB   256
#define HID   512
#define G4    2048
#define VOC   32000
#define SNBLK 64          // scan blocks
#define AUXBLK 84         // aux blocks (convB/zero + FC)
#define NSTEP (SENC + TDEC)
#define MROWS (BATCH * TDEC)   // 1984
#define MPAD  2048
#define KS16  (HID / 16)       // 32
#define EKS16 (EMB / 16)       // 16
#define NT8   (VOC / 8)        // 4000
#define NTILE ((MPAD / 128) * (VOC / 128))   // 16 * 250 = 4000

// ---------------- scratch ----------------
__device__ float  d_xp_enc[SENC * BATCH * G4];
__device__ float  d_xp_dec[TDEC * BATCH * G4];
__device__ __half d_hbuf[2][BATCH * HID];
__device__ __half d_hseq[MPAD * HID];            // t-major: m = t*64 + b
__device__ unsigned d_sync[96];                  // [0]=bar, [32]=aux, [64]=ticket (padded lines)

__device__ uint32_t d_Bf[NT8 * KS16 * 32 * 2];
__device__ uint32_t d_WihF[2 * 256 * EKS16 * 32 * 2];
__device__ uint32_t d_WhhF[2 * SNBLK * 4 * KS16 * 32 * 2];

// ---------------- helpers ----------------
__device__ __forceinline__ uint32_t smem_u32(const void* p) {
    uint32_t a;
    asm("{ .reg .u64 t; cvta.to.shared.u64 t, %1; cvt.u32.u64 %0, t; }"
        : "=r"(a) : "l"(p));
    return a;
}
#define CP_ASYNC16(dst, src) \
    asm volatile("cp.async.cg.shared.global [%0], [%1], 16;" \
                 :: "r"(dst), "l"(src) : "memory")
#define CP_COMMIT() asm volatile("cp.async.commit_group;" ::: "memory")
#define CP_WAIT1()  asm volatile("cp.async.wait_group 1;" ::: "memory")
#define CP_WAITN(n) asm volatile("cp.async.wait_group %0;" :: "n"(n) : "memory")

__device__ __forceinline__ uint32_t packh2(float x, float y) {
    __half2 h = __floats2half2_rn(x, y);
    return *(uint32_t*)&h;
}
__device__ __forceinline__ void mma_f16(float* c, const uint32_t* a,
                                        uint32_t b0, uint32_t b1)
{
    asm volatile("mma.sync.aligned.m16n8k16.row.col.f32.f16.f16.f32 "
                 "{%0,%1,%2,%3}, {%4,%5,%6,%7}, {%8,%9}, {%0,%1,%2,%3};"
                 : "+f"(c[0]), "+f"(c[1]), "+f"(c[2]), "+f"(c[3])
                 : "r"(a[0]), "r"(a[1]), "r"(a[2]), "r"(a[3]), "r"(b0), "r"(b1));
}
__device__ __forceinline__ void ldmatrix_x4(uint32_t& r0, uint32_t& r1,
                                            uint32_t& r2, uint32_t& r3, uint32_t addr)
{
    asm volatile("ldmatrix.sync.aligned.m8n8.x4.shared.b16 {%0,%1,%2,%3}, [%4];"
                 : "=r"(r0), "=r"(r1), "=r"(r2), "=r"(r3) : "r"(addr));
}

__device__ __forceinline__ void rel_add(unsigned* p) {
    asm volatile("red.release.gpu.global.add.u32 [%0], 1;" :: "l"(p) : "memory");
}
__device__ __forceinline__ unsigned acq_ld(const unsigned* p) {
    unsigned v;
    asm volatile("ld.acquire.gpu.global.u32 %0, [%1];" : "=r"(v) : "l"(p) : "memory");
    return v;
}
__device__ __forceinline__ void poll_tight(const unsigned* p, unsigned target) {
    while (acq_ld(p) < target) { }
}
__device__ __forceinline__ void poll_sleep(const unsigned* p, unsigned target) {
    while (acq_ld(p) < target) { __nanosleep(128); }
}

__device__ __forceinline__ float sigm(float x) {
    return __fdividef(1.0f, 1.0f + __expf(-x));
}
__device__ __forceinline__ float tanh_fast(float x) {
    return 1.0f - __fdividef(2.0f, __expf(2.0f * x) + 1.0f);
}

// ---------------- Wih -> fp16 fragments ----------------
__global__ __launch_bounds__(256) void convWih_frag_kernel(
    const float* __restrict__ encWih, const float* __restrict__ decWih)
{
    int idx = blockIdx.x * 256 + threadIdx.x;
    if (idx >= 2 * 256 * EKS16 * 32) return;
    int lane  = idx & 31;
    int ks    = (idx >> 5) & (EKS16 - 1);
    int nt    = (idx >> 9) & 255;
    int layer = idx >> 17;
    int g = lane >> 2, tig = lane & 3;
    const float* W = layer ? decWih : encWih;
    const float* row = W + (size_t)(nt * 8 + g) * EMB + ks * 16 + tig * 2;
    ((uint2*)d_WihF)[idx] = make_uint2(packh2(row[0], row[1]),
                                      packh2(row[8], row[9]));
}

// ---------------- xp via fp16 mma ----------------
#define XPP 264
#define XP_SMEM (64 * XPP * 2)

__global__ __launch_bounds__(256, 2) void xp_mma_kernel(
    const int*   __restrict__ src,  const int* __restrict__ tgt,
    const float* __restrict__ enc_emb, const float* __restrict__ dec_emb,
    const float* __restrict__ enc_bih, const float* __restrict__ enc_bhh,
    const float* __restrict__ dec_bih, const float* __restrict__ dec_bhh)
{
    extern __shared__ __half a_s[];

    const int tid  = threadIdx.x;
    const int wid  = tid >> 5;
    const int lane = tid & 31;
    const int n0   = blockIdx.x * 128;
    const int t    = blockIdx.y;

    const int*   toks; const float* emb; const float* bi; const float* bh;
    const uint32_t* WF; float* xp; int tloc, tstride;
    if (t < SENC) {
        toks = src; emb = enc_emb; bi = enc_bih; bh = enc_bhh;
        WF = d_WihF; xp = d_xp_enc + (size_t)t * BATCH * G4;
        tloc = t; tstride = SENC;
    } else {
        toks = tgt; emb = dec_emb; bi = dec_bih; bh = dec_bhh;
        WF = d_WihF + 256 * EKS16 * 32 * 2;
        xp = d_xp_dec + (size_t)(t - SENC) * BATCH * G4;
        tloc = t - SENC; tstride = 32;
    }

#pragma unroll
    for (int i = 0; i < 32; i++) {
        int q  = tid + i * 256;
        int r  = q >> 7;
        int c2 = q & 127;
        int tok = __ldg(toks + r * tstride + tloc);
        float2 v = __ldg((const float2*)(emb + (size_t)tok * EMB + c2 * 2));
        *(uint32_t*)&a_s[r * XPP + c2 * 2] = packh2(v.x, v.y);
    }
    __syncthreads();

    const int mt = wid >> 1;
    const int nh = wid & 1;
    const int g  = lane >> 2, tig = lane & 3;

    float acc[8][4];
#pragma unroll
    for (int nt = 0; nt < 8; nt++)
#pragma unroll
        for (int r = 0; r < 4; r++) acc[nt][r] = 0.0f;

    const int n8base = n0 / 8 + nh * 8;
    const __half* ap = &a_s[(mt * 16 + g) * XPP + tig * 2];

    for (int ks = 0; ks < EKS16; ks++) {
        uint32_t a[4];
        a[0] = *(const uint32_t*)(ap + ks * 16);
        a[2] = *(const uint32_t*)(ap + ks * 16 + 8);
        a[1] = *(const uint32_t*)(ap + ks * 16 + 8 * XPP);
        a[3] = *(const uint32_t*)(ap + ks * 16 + 8 * XPP + 8);
#pragma unroll
        for (int nt = 0; nt < 8; nt++) {
            uint2 b = __ldg((const uint2*)(WF +
                      (((size_t)(n8base + nt) * EKS16 + ks) * 32 + lane) * 2));
            mma_f16(acc[nt], a, b.x, b.y);
        }
    }

#pragma unroll
    for (int nt = 0; nt < 8; nt++) {
        int n = (n8base + nt) * 8 + tig * 2;
        float b0 = __ldg(bi + n) + __ldg(bh + n);
        float b1 = __ldg(bi + n + 1) + __ldg(bh + n + 1);
        int r0 = mt * 16 + g;
        *(float2*)(xp + (size_t)r0 * G4 + n) =
            make_float2(acc[nt][0] + b0, acc[nt][1] + b1);
        *(float2*)(xp + (size_t)(r0 + 8) * G4 + n) =
            make_float2(acc[nt][2] + b0, acc[nt][3] + b1);
    }
}

// ---------------- Whh -> gate-permuted fp16 fragments (+ reset sync cells) ----------------
__global__ __launch_bounds__(256) void convWhh_frag_kernel(
    const float* __restrict__ encWhh, const float* __restrict__ decWhh)
{
    if (blockIdx.x == 0 && threadIdx.x < 96) d_sync[threadIdx.x] = 0;

    int idx = blockIdx.x * 256 + threadIdx.x;
    if (idx >= 2 * SNBLK * 4 * KS16 * 32) return;
    int lane  = idx & 31;
    int ks    = (idx >> 5) & (KS16 - 1);
    int nt    = (idx >> 10) & 3;
    int bid   = (idx >> 12) & 63;
    int layer = idx >> 18;

    int g = lane >> 2, tig = lane & 3;
    int nn   = nt * 8 + g;
    int j    = bid * 8 + (nn >> 2);
    int gate = nn & 3;
    const float* W = layer ? decWhh : encWhh;
    const float* row = W + (size_t)(gate * HID + j) * HID + ks * 16 + tig * 2;
    ((uint2*)d_WhhF)[idx] = make_uint2(packh2(row[0], row[1]),
                                      packh2(row[8], row[9]));
}

// ---------------- fused scan + FC kernel ----------------
#define HPB   1040
#define WFU   (4 * KS16 * 32 * 2)                // 8192 u32
#define SCAN_SMEM 132112                         // 2*WFU*4 + 64*HPB (=132096) + 16 ticket
#define TICKET_OFF 132096

#define AS_PITCH 144                             // A tile row pitch (bytes)
#define AS_BYTES (128 * AS_PITCH)                // 18432
#define FCB_OFF  (2 * AS_BYTES)                  // B bufs at 36864 (+2*16384)

// FC tile worker: pulls tiles from ticket counter; A from d_hseq, B from d_Bf.
__device__ __forceinline__ void fc_tile_loop(
    char* smem, uint32_t sbase, const float* bias, float* out,
    int tid, int wid, int lane)
{
    volatile int* s_ticket = (volatile int*)(smem + TICKET_OFF);
    const uint32_t aB = sbase;
    const uint32_t bB = sbase + FCB_OFF;
    const int mtW = (wid >> 2) * 4;
    const int ntW = (wid & 3) * 4;
    const int g = lane >> 2, tig = lane & 3;
    const int b_ntL = tid >> 4, b_in = tid & 15;

    for (;;) {
        if (tid == 0) *s_ticket = (int)atomicAdd(&d_sync[64], 1u);
        __syncthreads();
        const int tile = *s_ticket;
        __syncthreads();
        if (tile >= NTILE) return;
        const int q    = tile / 250;
        const int ncol = tile - q * 250;
        const int m0   = q * 128;
        const int n0   = ncol * 128;

        // availability: hseq[t] visible once bar_ctr >= (67+t)*64
        if (tid == 0) {
            int tn = 2 * q + 1; if (tn > 30) tn = 30;
            poll_sleep(&d_sync[0], (unsigned)(67 + tn) * SNBLK);
        }
        __syncthreads();

        float acc[4][4][4];
#pragma unroll
        for (int mt = 0; mt < 4; mt++)
#pragma unroll
            for (int nt = 0; nt < 4; nt++)
#pragma unroll
                for (int r = 0; r < 4; r++) acc[mt][nt][r] = 0.0f;

#define LOADF(it, buf) do {                                                      \
    int _k64 = (it) * 64;                                                        \
    _Pragma("unroll")                                                            \
    for (int _c = 0; _c < 4; _c++) {                                             \
        int _ch = tid + _c * 256;                                                \
        int _r = _ch >> 3, _kc = _ch & 7;                                        \
        const char* _sa = (const char*)d_hseq +                                  \
            (((size_t)(m0 + _r) * HID) + _k64 + _kc * 8) * 2;                    \
        CP_ASYNC16(aB + (buf) * AS_BYTES + _r * AS_PITCH + _kc * 16, _sa);       \
    }                                                                            \
    { const uint32_t* _gb = d_Bf + (((size_t)(n0 / 8 + b_ntL) * KS16 + (it) * 4) * 64); \
      _Pragma("unroll")                                                          \
      for (int _c = 0; _c < 4; _c++)                                             \
          CP_ASYNC16(bB + (buf) * 16384 + (b_ntL * 4 + _c) * 256 + b_in * 16,    \
                     (const char*)(_gb + _c * 64 + b_in * 4)); }                 \
} while (0)

        LOADF(0, 0);
        CP_COMMIT();

        for (int it = 0; it < 8; it++) {
            const int buf = it & 1;
            if (it + 1 < 8) LOADF(it + 1, buf ^ 1);
            CP_COMMIT();
            CP_WAIT1();
            __syncthreads();

            const uint32_t aOff = aB + buf * AS_BYTES;
            const uint32_t bOff = bB + buf * 16384;
#pragma unroll
            for (int ks = 0; ks < 4; ks++) {
                uint32_t a[4][4];
#pragma unroll
                for (int mt = 0; mt < 4; mt++) {
                    uint32_t addr = aOff + ((mtW + mt) * 16 + (lane & 15)) * AS_PITCH
                                  + ks * 32 + (lane >> 4) * 16;
                    ldmatrix_x4(a[mt][0], a[mt][1], a[mt][2], a[mt][3], addr);
                }
                uint32_t b[4][2];
#pragma unroll
                for (int nt = 0; nt < 4; nt++) {
                    uint32_t addr = bOff + ((ntW + nt) * 4 + ks) * 256 + lane * 8;
                    asm volatile("ld.shared.v2.b32 {%0,%1}, [%2];"
                                 : "=r"(b[nt][0]), "=r"(b[nt][1]) : "r"(addr));
                }
#pragma unroll
                for (int mt = 0; mt < 4; mt++)
#pragma unroll
                    for (int nt = 0; nt < 4; nt++)
                        mma_f16(acc[mt][nt], a[mt], b[nt][0], b[nt][1]);
            }
            __syncthreads();
        }
#undef LOADF

        // epilogue: m = t*64 + b  ->  out[b][t+1][n]
#pragma unroll
        for (int mt = 0; mt < 4; mt++) {
#pragma unroll
            for (int half = 0; half < 2; half++) {
                int m = m0 + (mtW + mt) * 16 + g + half * 8;
                if (m >= MROWS) continue;
                int b  = m & 63;
                int tt = m >> 6;
                float* orow = out + ((size_t)b * 32 + tt + 1) * VOC;
#pragma unroll
                for (int nt = 0; nt < 4; nt++) {
                    int n = n0 + (ntW + nt) * 8 + tig * 2;
                    float b0 = __ldg(bias + n);
                    float b1 = __ldg(bias + n + 1);
                    float2 v = make_float2(acc[mt][nt][half * 2 + 0] + b0,
                                           acc[mt][nt][half * 2 + 1] + b1);
                    *(float2*)(orow + n) = v;
                }
            }
        }
    }
}

__global__ __launch_bounds__(256, 1) void scan_fused_kernel(
    const float* __restrict__ fcW, const float* __restrict__ fcB,
    float* __restrict__ out)
{
    extern __shared__ char scm[];
    const int tid = threadIdx.x;
    const int bid = blockIdx.x;
    const int wid  = tid >> 5;
    const int lane = tid & 31;
    const uint32_t sbase = smem_u32(scm);

    // ================= aux blocks =================
    if (bid >= SNBLK) {
        const int aid = (bid - SNBLK) * 256 + tid;
        const int astride = AUXBLK * 256;

        // zero out[:, 0, :]
        const float4 z4 = make_float4(0.f, 0.f, 0.f, 0.f);
        for (int i = aid; i < BATCH * (VOC / 4); i += astride) {
            int b  = i / (VOC / 4);
            int v4 = i - b * (VOC / 4);
            ((float4*)(out + (size_t)b * 32 * VOC))[v4] = z4;
        }
        // convB: fc_W -> fp16 fragment-major
        for (int i = aid; i < NT8 * KS16 * 32; i += astride) {
            int lane2 = i & 31;
            int ks    = (i >> 5) & (KS16 - 1);
            int nt    = i >> 10;
            int gg    = lane2 >> 2, tg = lane2 & 3;
            const float* row = fcW + (size_t)(nt * 8 + gg) * HID + ks * 16 + tg * 2;
            ((uint2*)d_Bf)[i] = make_uint2(packh2(row[0], row[1]),
                                           packh2(row[8], row[9]));
        }
        __syncthreads();
        if (tid == 0) {
            rel_add(&d_sync[32]);
            poll_sleep(&d_sync[32], AUXBLK);
        }
        __syncthreads();

        fc_tile_loop(scm, sbase, fcB, out, tid, wid, lane);
        return;
    }

    // ================= scan blocks =================
    uint32_t* wf = (uint32_t*)scm;
    char*     hs = scm + 2 * WFU * 4;
    const uint32_t hBase = sbase + 2 * WFU * 4;

    const int mt   = wid & 3;
    const int ntp  = (wid >> 2) * 2;
    const int g    = lane >> 2;
    const int tig  = lane & 3;
    const int odd  = lane & 1;

    const int myb  = mt * 16 + g + odd * 8;
    const int j0   = bid * 8 + ntp * 2 + (tig >> 1);
    const int j1   = j0 + 2;

    const uint32_t ldmBase = hBase + (uint32_t)((mt * 16 + (lane & 15)) * HPB
                                                + (lane >> 4) * 16);

    // h0 = 0
#pragma unroll
    for (int i = 0; i < 2; i++) {
        int e = tid + i * 256;
        d_hbuf[0][(e >> 3) * HID + bid * 8 + (e & 7)] = __float2half(0.0f);
    }
    float c0 = 0.0f, c1 = 0.0f;

    {   // both layers' Whh frags
        const uint4* se = (const uint4*)(d_WhhF + (size_t)bid * WFU);
        const uint4* sd = (const uint4*)(d_WhhF + (size_t)(SNBLK + bid) * WFU);
#pragma unroll
        for (int i = 0; i < 8; i++) {
            ((uint4*)wf)[tid + i * 256]        = se[tid + i * 256];
            ((uint4*)wf)[2048 + tid + i * 256] = sd[tid + i * 256];
        }
    }
    __syncthreads();

    unsigned bar_target = SNBLK;
    if (tid == 0) { rel_add(&d_sync[0]); poll_tight(&d_sync[0], bar_target); }
    bar_target += SNBLK;
    __syncthreads();

    // prefetch xp for step 0
    float xi0, xf0, xg0, xo0, xi1, xf1, xg1, xo1;
    {
        const float* xb0 = d_xp_enc + (size_t)myb * G4 + j0;
        const float* xb1 = d_xp_enc + (size_t)myb * G4 + j1;
        xi0 = __ldcg(xb0);        xf0 = __ldcg(xb0 + 512);
        xg0 = __ldcg(xb0 + 1024); xo0 = __ldcg(xb0 + 1536);
        xi1 = __ldcg(xb1);        xf1 = __ldcg(xb1 + 512);
        xg1 = __ldcg(xb1 + 1024); xo1 = __ldcg(xb1 + 1536);
    }

    for (int step = 0; step < NSTEP; step++) {
        const __half* __restrict__ hprev = d_hbuf[step & 1];
        __half*       __restrict__ hnext = d_hbuf[(step & 1) ^ 1];
        const uint32_t* wfL = wf + ((step < SENC) ? 0 : WFU);

#pragma unroll
        for (int ch = 0; ch < 2; ch++) {
#pragma unroll
            for (int i = 0; i < 8; i++) {
                int q  = tid + i * 256;
                int r  = q >> 5;
                int cb = (q & 31) * 16;
                CP_ASYNC16(hBase + r * HPB + ch * 512 + cb,
                           (const char*)hprev + (size_t)r * 1024 + ch * 512 + cb);
            }
            CP_COMMIT();
        }

        float acc[2][4];
#pragma unroll
        for (int u = 0; u < 2; u++)
#pragma unroll
            for (int r = 0; r < 4; r++) acc[u][r] = 0.0f;

#pragma unroll
        for (int ch = 0; ch < 2; ch++) {
            if (ch == 0) CP_WAITN(1);
            else CP_WAITN(0);
            __syncthreads();

            const uint32_t aAddr = ldmBase + ch * 512;
            const uint32_t* bp0 = wfL + ((ntp * KS16 + ch * 16) * 32 + lane) * 2;
            const uint32_t* bp1 = wfL + (((ntp + 1) * KS16 + ch * 16) * 32 + lane) * 2;
#pragma unroll
            for (int k2 = 0; k2 < 16; k2++) {
                uint32_t a[4];
                ldmatrix_x4(a[0], a[1], a[2], a[3], aAddr + k2 * 32);
                uint2 b0 = *(const uint2*)(bp0 + k2 * 64);
                uint2 b1 = *(const uint2*)(bp1 + k2 * 64);
                mma_f16(acc[0], a, b0.x, b0.y);
                mma_f16(acc[1], a, b1.x, b1.y);
            }
        }

        __half hr0h, hr1h;
#pragma unroll
        for (int u = 0; u < 2; u++) {
            float* a = acc[u];
            float o0 = __shfl_xor_sync(0xFFFFFFFFu, a[0], 1);
            float o1 = __shfl_xor_sync(0xFFFFFFFFu, a[1], 1);
            float o2 = __shfl_xor_sync(0xFFFFFFFFu, a[2], 1);
            float o3 = __shfl_xor_sync(0xFFFFFFFFu, a[3], 1);
            float pi, pf, pg, po;
            if (!odd) { pi = a[0]; pf = a[1]; pg = o0;   po = o1;   }
            else      { pi = o2;   pf = o3;   pg = a[2]; po = a[3]; }

            if (u == 0) { pi += xi0; pf += xf0; pg += xg0; po += xo0; }
            else        { pi += xi1; pf += xf1; pg += xg1; po += xo1; }

            float& cc = (u == 0) ? c0 : c1;
            cc = sigm(pf) * cc + sigm(pi) * tanh_fast(pg);
            __half hr = __float2half_rn(sigm(po) * tanh_fast(cc));

            int j = (u == 0) ? j0 : j1;
            __stcg((short*)&hnext[(size_t)myb * HID + j], *(short*)&hr);
            if (u == 0) hr0h = hr; else hr1h = hr;
        }

        // ---- barrier with work in the poll shadow (every step) ----
        __syncthreads();
        if (tid == 0) rel_add(&d_sync[0]);      // arrive

        if (step >= SENC) {
            int t = step - SENC;
            size_t m = (size_t)t * 64 + myb;    // t-major hseq
            d_hseq[m * HID + j0] = hr0h;
            d_hseq[m * HID + j1] = hr1h;
        }
        if (step + 1 < NSTEP) {
            const float* xp_n = (step + 1 < SENC)
                ? (d_xp_enc + (size_t)(step + 1) * BATCH * G4)
                : (d_xp_dec + (size_t)(step + 1 - SENC) * BATCH * G4);
            const float* xb0 = xp_n + (size_t)myb * G4 + j0;
            const float* xb1 = xp_n + (size_t)myb * G4 + j1;
            xi0 = __ldcg(xb0);        xf0 = __ldcg(xb0 + 512);
            xg0 = __ldcg(xb0 + 1024); xo0 = __ldcg(xb0 + 1536);
            xi1 = __ldcg(xb1);        xf1 = __ldcg(xb1 + 512);
            xg1 = __ldcg(xb1 + 1024); xo1 = __ldcg(xb1 + 1536);
        }

        if (tid == 0) poll_tight(&d_sync[0], bar_target);
        bar_target += SNBLK;
        __syncthreads();
    }

    // extra release: makes last-step hseq stores (issued post-arrive) visible
    __syncthreads();
    if (tid == 0) rel_add(&d_sync[0]);          // ctr -> 97*64 eventually

    // ensure convB done (long since), then join the FC tile queue
    if (tid == 0) poll_sleep(&d_sync[32], AUXBLK);
    __syncthreads();

    fc_tile_loop(scm, sbase, fcB, out, tid, wid, lane);
}

// ---------------- launch ----------------
extern "C" void kernel_launch(void* const* d_in, const int* in_sizes, int n_in,
                              void* d_out, int out_size)
{
    const int*   src     = (const int*)  d_in[0];
    const int*   tgt     = (const int*)  d_in[1];
    const float* enc_emb = (const float*)d_in[2];
    const float* dec_emb = (const float*)d_in[3];
    const float* enc_Wih = (const float*)d_in[4];
    const float* enc_Whh = (const float*)d_in[5];
    const float* enc_bih = (const float*)d_in[6];
    const float* enc_bhh = (const float*)d_in[7];
    const float* dec_Wih = (const float*)d_in[8];
    const float* dec_Whh = (const float*)d_in[9];
    const float* dec_bih = (const float*)d_in[10];
    const float* dec_bhh = (const float*)d_in[11];
    const float* fc_W    = (const float*)d_in[12];
    const float* fc_b    = (const float*)d_in[13];
    float* out = (float*)d_out;

    static int attr_set = 0;
    if (!attr_set) {
        cudaFuncSetAttribute(scan_fused_kernel,
                             cudaFuncAttributeMaxDynamicSharedMemorySize, SCAN_SMEM);
        cudaFuncSetAttribute(xp_mma_kernel,
                             cudaFuncAttributeMaxDynamicSharedMemorySize, XP_SMEM);
        attr_set = 1;
    }

    convWih_frag_kernel<<<(2 * 256 * EKS16 * 32 + 255) / 256, 256>>>(enc_Wih, dec_Wih);
    xp_mma_kernel<<<dim3(16, SENC + TDEC), 256, XP_SMEM>>>(
        src, tgt, enc_emb, dec_emb, enc_bih, enc_bhh, dec_bih, dec_bhh);
    convWhh_frag_kernel<<<(2 * SNBLK * 4 * KS16 * 32 + 255) / 256, 256>>>(enc_Whh, dec_Whh);
    scan_fused_kernel<<<SNBLK + AUXBLK, 256, SCAN_SMEM>>>(fc_W, fc_b, out);
}